// round 3
// baseline (speedup 1.0000x reference)
#include <cuda_runtime.h>
#include <cstdint>
#include <cstddef>

// Problem constants
#define Bb      4
#define NN      2048
#define IN1     128
#define HD      64
#define NHEAD   4
#define NWORDS  (NN / 32)   // 64 u32 words per adjacency row

// -------- scratch (device globals; no allocation allowed) --------
static __device__ float    g_h1[Bb * NHEAD * NN * HD];      // [b,h,n,d]  8 MB
static __device__ float    g_s1[Bb * NHEAD * NN];
static __device__ float    g_t1[Bb * NHEAD * NN];
static __device__ unsigned g_adjb[Bb * NN * NWORDS];        // bit-packed adjacency, 2 MB
static __device__ float    g_hcat[Bb * NN * NHEAD * HD];    // [b,n,h*64+d] 8 MB
static __device__ float    g_h2[Bb * NN * HD];              // 2 MB
static __device__ float    g_s2[Bb * NN];
static __device__ float    g_t2[Bb * NN];

// ---------------- pack adj int32 -> bits (one 67MB pass) ----------------
__global__ __launch_bounds__(256) void k_pack(const int* __restrict__ adj) {
    size_t idx = (size_t)blockIdx.x * blockDim.x + threadIdx.x;  // over B*N*N
    unsigned v = (adj[idx] != 0) ? 1u : 0u;
    unsigned m = __ballot_sync(0xffffffffu, v);
    if ((threadIdx.x & 31) == 0) g_adjb[idx >> 5] = m;
}

// ---------------- tiled GEMM: C[(b*heads+h)*N + m][64] = A[b][m][K] @ W[h][K][64] ----
// L==1: A = x (param), K=128, heads=4, C=g_h1
// L==2: A = g_hcat,    K=256, heads=1, C=g_h2
template <int L>
__global__ __launch_bounds__(256) void k_gemm(const float* __restrict__ Ain,
                                              const float* __restrict__ Wm) {
    constexpr int K     = (L == 1) ? IN1 : (NHEAD * HD);
    constexpr int HEADS = (L == 1) ? NHEAD : 1;
    __shared__ float xs[128][33];
    __shared__ float ws[32][68];

    const int m0  = blockIdx.x * 128;
    const int h   = blockIdx.y;
    const int b   = blockIdx.z;
    const int tid = threadIdx.x;
    const int tx  = tid & 15, ty = tid >> 4;

    const float* Ab = ((L == 1) ? Ain : g_hcat) + (size_t)b * NN * K;
    const float* Wb = Wm + (size_t)h * K * 64;
    float*       Cb = ((L == 1) ? g_h1 : g_h2);

    float acc[8][4];
#pragma unroll
    for (int a = 0; a < 8; a++)
#pragma unroll
        for (int c = 0; c < 4; c++) acc[a][c] = 0.f;

    for (int kc = 0; kc < K; kc += 32) {
        __syncthreads();
#pragma unroll 4
        for (int idx = tid; idx < 128 * 32; idx += 256) {
            int r = idx >> 5, c = idx & 31;
            xs[r][c] = Ab[(size_t)(m0 + r) * K + kc + c];
        }
#pragma unroll 2
        for (int idx = tid; idx < 32 * 64; idx += 256) {
            int r = idx >> 6, c = idx & 63;
            ws[r][c] = Wb[(size_t)(kc + r) * 64 + c];
        }
        __syncthreads();
#pragma unroll
        for (int k = 0; k < 32; k++) {
            float4 w4 = *(const float4*)&ws[k][tx * 4];
#pragma unroll
            for (int a = 0; a < 8; a++) {
                float xv = xs[ty * 8 + a][k];
                acc[a][0] = fmaf(xv, w4.x, acc[a][0]);
                acc[a][1] = fmaf(xv, w4.y, acc[a][1]);
                acc[a][2] = fmaf(xv, w4.z, acc[a][2]);
                acc[a][3] = fmaf(xv, w4.w, acc[a][3]);
            }
        }
    }
#pragma unroll
    for (int a = 0; a < 8; a++) {
        float4 v = make_float4(acc[a][0], acc[a][1], acc[a][2], acc[a][3]);
        *(float4*)&Cb[((size_t)(b * HEADS + h) * NN + m0 + ty * 8 + a) * 64 + tx * 4] = v;
    }
}

// ---------------- s/t vectors: s = h . a[0:64], t = h . a[64:128] ----------------
template <int L>
__global__ __launch_bounds__(256) void k_st(const float* __restrict__ av) {
    constexpr int HEADS = (L == 1) ? NHEAD : 1;
    const float* Hm = (L == 1) ? g_h1 : g_h2;
    float* Sv = (L == 1) ? g_s1 : g_s2;
    float* Tv = (L == 1) ? g_t1 : g_t2;

    int warp = (int)((blockIdx.x * blockDim.x + threadIdx.x) >> 5);
    int lane = threadIdx.x & 31;
    int head = (warp / NN) % HEADS;
    const float* hrow = Hm + (size_t)warp * 64;
    float h0 = hrow[lane], h1 = hrow[lane + 32];
    const float* a = av + head * 128;
    float s = h0 * a[lane] + h1 * a[lane + 32];
    float t = h0 * a[64 + lane] + h1 * a[96 + lane];
#pragma unroll
    for (int off = 16; off; off >>= 1) {
        s += __shfl_xor_sync(0xffffffffu, s, off);
        t += __shfl_xor_sync(0xffffffffu, t, off);
    }
    if (lane == 0) { Sv[warp] = s; Tv[warp] = t; }
}

// ---------------- flash-GAT attention: out_i = sum_j P_ij h_j / Z_i ----------------
// P_ij = adj_ij * exp(leaky_relu(s_i + t_j, 0.2)); no max-shift needed (|e| small).
// 64x64 output tile per block; 256 threads as 16x16; 4x4 register micro-tile;
// inner product uses packed fma.rn.f32x2 (FFMA2) for 2x fp32 FMA throughput.
template <int L>
__global__ __launch_bounds__(256) void k_att(float* __restrict__ OutParam) {
    constexpr int HEADS   = (L == 1) ? NHEAD : 1;
    constexpr int FSTRIDE = (L == 1) ? (NHEAD * HD) : HD;
    const float* Hm = (L == 1) ? g_h1 : g_h2;
    const float* Sv = (L == 1) ? g_s1 : g_s2;
    const float* Tv = (L == 1) ? g_t1 : g_t2;
    float* Out = (L == 1) ? g_hcat : OutParam;

    __shared__ float h_s[64][66];   // [jj][d], row pad even -> 8B-aligned float2 reads
    __shared__ float p_s[64][65];   // [ii][jj]
    __shared__ float s_sh[64], t_sh[64], z_sh[64];

    const int tid = threadIdx.x;
    const int tx  = tid & 15, ty = tid >> 4;
    const int i0  = blockIdx.x * 64;
    const int h   = blockIdx.y;
    const int b   = blockIdx.z;
    const int bh  = b * HEADS + h;

    const float* Hb = Hm + (size_t)bh * NN * 64;
    const float* Sb = Sv + (size_t)bh * NN;
    const float* Tb = Tv + (size_t)bh * NN;
    const unsigned* adjb = g_adjb + (size_t)b * NN * NWORDS;

    if (tid < 64) s_sh[tid] = Sb[i0 + tid];

    unsigned long long acc01[4] = {0ull, 0ull, 0ull, 0ull};
    unsigned long long acc23[4] = {0ull, 0ull, 0ull, 0ull};
    float zacc[4] = {0.f, 0.f, 0.f, 0.f};

    for (int j0 = 0; j0 < NN; j0 += 64) {
        __syncthreads();   // previous tile fully consumed; s_sh visible on first iter
        if (tid < 64) t_sh[tid] = Tb[j0 + tid];
#pragma unroll 4
        for (int idx = tid; idx < 64 * 64; idx += 256) {
            int r = idx >> 6, c = idx & 63;
            h_s[r][c] = Hb[(size_t)(j0 + r) * 64 + c];
        }
        __syncthreads();

        // generate P tile + accumulate row sums
#pragma unroll
        for (int a = 0; a < 4; a++) {
            int ii = ty * 4 + a;
            float si = s_sh[ii];
            unsigned w = adjb[(size_t)(i0 + ii) * NWORDS + (j0 >> 5) + (tx >> 3)];
#pragma unroll
            for (int c = 0; c < 4; c++) {
                int jj = tx * 4 + c;
                float e = si + t_sh[jj];
                e = (e > 0.f) ? e : 0.2f * e;
                float p = ((w >> (jj & 31)) & 1u) ? __expf(e) : 0.f;
                p_s[ii][jj] = p;
                zacc[a] += p;
            }
        }
        __syncthreads();

        // 64x64x64 tile inner product via packed f32x2 FMA
#pragma unroll 8
        for (int jj = 0; jj < 64; jj++) {
            unsigned long long hv01 = *(const unsigned long long*)&h_s[jj][tx * 4];
            unsigned long long hv23 = *(const unsigned long long*)&h_s[jj][tx * 4 + 2];
#pragma unroll
            for (int a = 0; a < 4; a++) {
                float pv = p_s[ty * 4 + a][jj];
                unsigned long long pv2;
                asm("mov.b64 %0, {%1, %1};" : "=l"(pv2) : "f"(pv));
                asm("fma.rn.f32x2 %0, %1, %2, %0;" : "+l"(acc01[a]) : "l"(pv2), "l"(hv01));
                asm("fma.rn.f32x2 %0, %1, %2, %0;" : "+l"(acc23[a]) : "l"(pv2), "l"(hv23));
            }
        }
    }

    // reduce Z across the 16 tx lanes that share each row
#pragma unroll
    for (int a = 0; a < 4; a++) {
        float z = zacc[a];
#pragma unroll
        for (int off = 8; off; off >>= 1) z += __shfl_down_sync(0xffffffffu, z, off, 16);
        if (tx == 0) z_sh[ty * 4 + a] = z;
    }
    __syncthreads();

#pragma unroll
    for (int a = 0; a < 4; a++) {
        int ii = ty * 4 + a;
        float rz = __fdividef(1.f, z_sh[ii]);
        float2 v01, v23;
        asm("mov.b64 {%0, %1}, %2;" : "=f"(v01.x), "=f"(v01.y) : "l"(acc01[a]));
        asm("mov.b64 {%0, %1}, %2;" : "=f"(v23.x), "=f"(v23.y) : "l"(acc23[a]));
        float* o = Out + ((size_t)b * NN + i0 + ii) * FSTRIDE + h * 64 + tx * 4;
        o[0] = v01.x * rz;
        o[1] = v01.y * rz;
        o[2] = v23.x * rz;
        o[3] = v23.y * rz;
    }
}

// ---------------- launch ----------------
extern "C" void kernel_launch(void* const* d_in, const int* in_sizes, int n_in,
                              void* d_out, int out_size) {
    const float* x       = (const float*)d_in[0];
    const int*   adj     = (const int*)d_in[1];
    const float* W_heads = (const float*)d_in[2];
    const float* a_heads = (const float*)d_in[3];
    const float* W_out   = (const float*)d_in[4];
    const float* a_out   = (const float*)d_in[5];
    float*       out     = (float*)d_out;

    // 1) pack adjacency to bits (read 67MB once)
    k_pack<<<(Bb * NN * (NN / 256)), 256>>>(adj);

    // 2) layer-1 projection h1 = x @ W_heads  (per head)
    k_gemm<1><<<dim3(NN / 128, NHEAD, Bb), 256>>>(x, W_heads);

    // 3) layer-1 s,t
    k_st<1><<<(Bb * NHEAD * NN) / 8, 256>>>(a_heads);

    // 4) layer-1 attention -> g_hcat [B,N,256]
    k_att<1><<<dim3(NN / 64, NHEAD, Bb), 256>>>(nullptr);

    // 5) layer-2 projection h2 = hcat @ W_out
    k_gemm<2><<<dim3(NN / 128, 1, Bb), 256>>>(nullptr, W_out);

    // 6) layer-2 s,t
    k_st<2><<<(Bb * NN) / 8, 256>>>(a_out);

    // 7) layer-2 attention -> d_out [B,N,64]
    k_att<2><<<dim3(NN / 64, 1, Bb), 256>>>(out);
}

// round 4
// speedup vs baseline: 1.0043x; 1.0043x over previous
#include <cuda_runtime.h>
#include <cstdint>
#include <cstddef>

// Problem constants
#define Bb      4
#define NN      2048
#define IN1     128
#define HD      64
#define NHEAD   4
#define NWORDS  (NN / 32)   // 64 u32 words per adjacency row

// -------- scratch (device globals; no allocation allowed) --------
static __device__ float    g_h1[Bb * NHEAD * NN * HD];      // [b,h,n,d]  8 MB
static __device__ float    g_s1[Bb * NHEAD * NN];
static __device__ float    g_t1[Bb * NHEAD * NN];
static __device__ unsigned g_adjb[Bb * NN * NWORDS];        // bit-packed adjacency, 2 MB
static __device__ float    g_hcat[Bb * NN * NHEAD * HD];    // [b,n,h*64+d] 8 MB
static __device__ float    g_h2[Bb * NN * HD];              // 2 MB
static __device__ float    g_s2[Bb * NN];
static __device__ float    g_t2[Bb * NN];

// ---------------- pack adj int32 -> bits (one 67MB pass) ----------------
__global__ __launch_bounds__(256) void k_pack(const int* __restrict__ adj) {
    size_t idx = (size_t)blockIdx.x * blockDim.x + threadIdx.x;  // over B*N*N
    unsigned v = (adj[idx] != 0) ? 1u : 0u;
    unsigned m = __ballot_sync(0xffffffffu, v);
    if ((threadIdx.x & 31) == 0) g_adjb[idx >> 5] = m;
}

// ---------------- tiled GEMM: C[(b*heads+h)*N + m][64] = A[b][m][K] @ W[h][K][64] ----
// L==1: A = x (param), K=128, heads=4, C=g_h1
// L==2: A = g_hcat,    K=256, heads=1, C=g_h2
template <int L>
__global__ __launch_bounds__(256) void k_gemm(const float* __restrict__ Ain,
                                              const float* __restrict__ Wm) {
    constexpr int K     = (L == 1) ? IN1 : (NHEAD * HD);
    constexpr int HEADS = (L == 1) ? NHEAD : 1;
    __shared__ float xs[128][33];
    __shared__ float ws[32][68];

    const int m0  = blockIdx.x * 128;
    const int h   = blockIdx.y;
    const int b   = blockIdx.z;
    const int tid = threadIdx.x;
    const int tx  = tid & 15, ty = tid >> 4;

    const float* Ab = ((L == 1) ? Ain : g_hcat) + (size_t)b * NN * K;
    const float* Wb = Wm + (size_t)h * K * 64;
    float*       Cb = ((L == 1) ? g_h1 : g_h2);

    float acc[8][4];
#pragma unroll
    for (int a = 0; a < 8; a++)
#pragma unroll
        for (int c = 0; c < 4; c++) acc[a][c] = 0.f;

    for (int kc = 0; kc < K; kc += 32) {
        __syncthreads();
#pragma unroll 4
        for (int idx = tid; idx < 128 * 32; idx += 256) {
            int r = idx >> 5, c = idx & 31;
            xs[r][c] = Ab[(size_t)(m0 + r) * K + kc + c];
        }
#pragma unroll 2
        for (int idx = tid; idx < 32 * 64; idx += 256) {
            int r = idx >> 6, c = idx & 63;
            ws[r][c] = Wb[(size_t)(kc + r) * 64 + c];
        }
        __syncthreads();
#pragma unroll
        for (int k = 0; k < 32; k++) {
            float4 w4 = *(const float4*)&ws[k][tx * 4];
#pragma unroll
            for (int a = 0; a < 8; a++) {
                float xv = xs[ty * 8 + a][k];
                acc[a][0] = fmaf(xv, w4.x, acc[a][0]);
                acc[a][1] = fmaf(xv, w4.y, acc[a][1]);
                acc[a][2] = fmaf(xv, w4.z, acc[a][2]);
                acc[a][3] = fmaf(xv, w4.w, acc[a][3]);
            }
        }
    }
#pragma unroll
    for (int a = 0; a < 8; a++) {
        float4 v = make_float4(acc[a][0], acc[a][1], acc[a][2], acc[a][3]);
        *(float4*)&Cb[((size_t)(b * HEADS + h) * NN + m0 + ty * 8 + a) * 64 + tx * 4] = v;
    }
}

// ---------------- s/t vectors: s = h . a[0:64], t = h . a[64:128] ----------------
template <int L>
__global__ __launch_bounds__(256) void k_st(const float* __restrict__ av) {
    constexpr int HEADS = (L == 1) ? NHEAD : 1;
    const float* Hm = (L == 1) ? g_h1 : g_h2;
    float* Sv = (L == 1) ? g_s1 : g_s2;
    float* Tv = (L == 1) ? g_t1 : g_t2;

    int warp = (int)((blockIdx.x * blockDim.x + threadIdx.x) >> 5);
    int lane = threadIdx.x & 31;
    int head = (warp / NN) % HEADS;
    const float* hrow = Hm + (size_t)warp * 64;
    float h0 = hrow[lane], h1 = hrow[lane + 32];
    const float* a = av + head * 128;
    float s = h0 * a[lane] + h1 * a[lane + 32];
    float t = h0 * a[64 + lane] + h1 * a[96 + lane];
#pragma unroll
    for (int off = 16; off; off >>= 1) {
        s += __shfl_xor_sync(0xffffffffu, s, off);
        t += __shfl_xor_sync(0xffffffffu, t, off);
    }
    if (lane == 0) { Sv[warp] = s; Tv[warp] = t; }
}

// ---------------- flash-GAT attention: out_i = sum_j P_ij h_j / Z_i ----------------
// P_ij = adj_ij * exp(leaky_relu(s_i + t_j, 0.2)); no max-shift needed (|e| small).
// 64x64 output tile per block; 256 threads as 16x16; 4x4 register micro-tile;
// inner product uses packed fma.rn.f32x2 (FFMA2) for 2x fp32 FMA throughput.
template <int L>
__global__ __launch_bounds__(256) void k_att(float* __restrict__ OutParam) {
    constexpr int HEADS   = (L == 1) ? NHEAD : 1;
    constexpr int FSTRIDE = (L == 1) ? (NHEAD * HD) : HD;
    const float* Hm = (L == 1) ? g_h1 : g_h2;
    const float* Sv = (L == 1) ? g_s1 : g_s2;
    const float* Tv = (L == 1) ? g_t1 : g_t2;
    float* Out = (L == 1) ? g_hcat : OutParam;

    __shared__ float h_s[64][66];   // [jj][d], row pad even -> 8B-aligned float2 reads
    __shared__ float p_s[64][65];   // [ii][jj]
    __shared__ float s_sh[64], t_sh[64], z_sh[64];

    const int tid = threadIdx.x;
    const int tx  = tid & 15, ty = tid >> 4;
    const int i0  = blockIdx.x * 64;
    const int h   = blockIdx.y;
    const int b   = blockIdx.z;
    const int bh  = b * HEADS + h;

    const float* Hb = Hm + (size_t)bh * NN * 64;
    const float* Sb = Sv + (size_t)bh * NN;
    const float* Tb = Tv + (size_t)bh * NN;
    const unsigned* adjb = g_adjb + (size_t)b * NN * NWORDS;

    if (tid < 64) s_sh[tid] = Sb[i0 + tid];

    unsigned long long acc01[4] = {0ull, 0ull, 0ull, 0ull};
    unsigned long long acc23[4] = {0ull, 0ull, 0ull, 0ull};
    float zacc[4] = {0.f, 0.f, 0.f, 0.f};

    for (int j0 = 0; j0 < NN; j0 += 64) {
        __syncthreads();   // previous tile fully consumed; s_sh visible on first iter
        if (tid < 64) t_sh[tid] = Tb[j0 + tid];
#pragma unroll 4
        for (int idx = tid; idx < 64 * 64; idx += 256) {
            int r = idx >> 6, c = idx & 63;
            h_s[r][c] = Hb[(size_t)(j0 + r) * 64 + c];
        }
        __syncthreads();

        // generate P tile + accumulate row sums
#pragma unroll
        for (int a = 0; a < 4; a++) {
            int ii = ty * 4 + a;
            float si = s_sh[ii];
            unsigned w = adjb[(size_t)(i0 + ii) * NWORDS + (j0 >> 5) + (tx >> 3)];
#pragma unroll
            for (int c = 0; c < 4; c++) {
                int jj = tx * 4 + c;
                float e = si + t_sh[jj];
                e = (e > 0.f) ? e : 0.2f * e;
                float p = ((w >> (jj & 31)) & 1u) ? __expf(e) : 0.f;
                p_s[ii][jj] = p;
                zacc[a] += p;
            }
        }
        __syncthreads();

        // 64x64x64 tile inner product via packed f32x2 FMA
#pragma unroll 8
        for (int jj = 0; jj < 64; jj++) {
            unsigned long long hv01 = *(const unsigned long long*)&h_s[jj][tx * 4];
            unsigned long long hv23 = *(const unsigned long long*)&h_s[jj][tx * 4 + 2];
#pragma unroll
            for (int a = 0; a < 4; a++) {
                float pv = p_s[ty * 4 + a][jj];
                unsigned long long pv2;
                asm("mov.b64 %0, {%1, %1};" : "=l"(pv2) : "f"(pv));
                asm("fma.rn.f32x2 %0, %1, %2, %0;" : "+l"(acc01[a]) : "l"(pv2), "l"(hv01));
                asm("fma.rn.f32x2 %0, %1, %2, %0;" : "+l"(acc23[a]) : "l"(pv2), "l"(hv23));
            }
        }
    }

    // reduce Z across the 16 tx lanes that share each row
#pragma unroll
    for (int a = 0; a < 4; a++) {
        float z = zacc[a];
#pragma unroll
        for (int off = 8; off; off >>= 1) z += __shfl_down_sync(0xffffffffu, z, off, 16);
        if (tx == 0) z_sh[ty * 4 + a] = z;
    }
    __syncthreads();

#pragma unroll
    for (int a = 0; a < 4; a++) {
        int ii = ty * 4 + a;
        float rz = __fdividef(1.f, z_sh[ii]);
        float2 v01, v23;
        asm("mov.b64 {%0, %1}, %2;" : "=f"(v01.x), "=f"(v01.y) : "l"(acc01[a]));
        asm("mov.b64 {%0, %1}, %2;" : "=f"(v23.x), "=f"(v23.y) : "l"(acc23[a]));
        float* o = Out + ((size_t)b * NN + i0 + ii) * FSTRIDE + h * 64 + tx * 4;
        o[0] = v01.x * rz;
        o[1] = v01.y * rz;
        o[2] = v23.x * rz;
        o[3] = v23.y * rz;
    }
}

// ---------------- launch ----------------
extern "C" void kernel_launch(void* const* d_in, const int* in_sizes, int n_in,
                              void* d_out, int out_size) {
    const float* x       = (const float*)d_in[0];
    const int*   adj     = (const int*)d_in[1];
    const float* W_heads = (const float*)d_in[2];
    const float* a_heads = (const float*)d_in[3];
    const float* W_out   = (const float*)d_in[4];
    const float* a_out   = (const float*)d_in[5];
    float*       out     = (float*)d_out;

    // 1) pack adjacency to bits (read 67MB once)
    k_pack<<<(Bb * NN * (NN / 256)), 256>>>(adj);

    // 2) layer-1 projection h1 = x @ W_heads  (per head)
    k_gemm<1><<<dim3(NN / 128, NHEAD, Bb), 256>>>(x, W_heads);

    // 3) layer-1 s,t
    k_st<1><<<(Bb * NHEAD * NN) / 8, 256>>>(a_heads);

    // 4) layer-1 attention -> g_hcat [B,N,256]
    k_att<1><<<dim3(NN / 64, NHEAD, Bb), 256>>>(nullptr);

    // 5) layer-2 projection h2 = hcat @ W_out
    k_gemm<2><<<dim3(NN / 128, 1, Bb), 256>>>(nullptr, W_out);

    // 6) layer-2 s,t
    k_st<2><<<(Bb * NN) / 8, 256>>>(a_out);

    // 7) layer-2 attention -> d_out [B,N,64]
    k_att<2><<<dim3(NN / 64, 1, Bb), 256>>>(out);
}